// round 9
// baseline (speedup 1.0000x reference)
#include <cuda_runtime.h>
#include <cuda_bf16.h>
#include <math.h>

// Batched Kabsch RMSD — single fused kernel:
//  - warp-per-batch streaming reduction (16 x 6 LDG.128 per lane, unroll 4)
//  - warp-local reduce; lane 0 runs fp32 closed-form 3x3 eigensolve and
//    atomically accumulates rmsd into g_sum (overlapped with other CTAs' streaming)
//  - last CTA writes out[0] = g_sum/B and resets accumulators for graph replay

#define NPTS 2048

__device__ float g_sum = 0.f;           // rmsd accumulator, reset each launch
__device__ unsigned int g_ctr = 0;      // CTA arrival counter, reset each launch

__device__ __forceinline__ float warp_sum(float v) {
    #pragma unroll
    for (int o = 16; o > 0; o >>= 1)
        v += __shfl_down_sync(0xffffffffu, v, o);
    return v;
}

__global__ __launch_bounds__(256, 4)
void kabsch_kernel(const float* __restrict__ P,
                   const float* __restrict__ Q,
                   float* __restrict__ out,
                   int B, int ncta)
{
    const int lane = threadIdx.x & 31;
    const int wid  = threadIdx.x >> 5;
    const int b    = blockIdx.x * 8 + wid;

    const float4* pb = reinterpret_cast<const float4*>(P + (size_t)b * (NPTS * 3));
    const float4* qb = reinterpret_cast<const float4*>(Q + (size_t)b * (NPTS * 3));

    // acc: [0..2]=sum_p, [3..5]=sum_q, [6]=sum|p|^2, [7]=sum|q|^2,
    //      [8..16]=sum p_a*q_b (row-major)
    float acc[17];
    #pragma unroll
    for (int i = 0; i < 17; i++) acc[i] = 0.f;

    #pragma unroll 4
    for (int j = 0; j < 16; j++) {
        const int g = j * 32 + lane;              // group of 4 points
        float4 pA = __ldcs(&pb[3*g+0]);
        float4 pB = __ldcs(&pb[3*g+1]);
        float4 pC = __ldcs(&pb[3*g+2]);
        float4 qA = __ldcs(&qb[3*g+0]);
        float4 qB = __ldcs(&qb[3*g+1]);
        float4 qC = __ldcs(&qb[3*g+2]);

        float px[4] = {pA.x, pA.w, pB.z, pC.y};
        float py[4] = {pA.y, pB.x, pB.w, pC.z};
        float pz[4] = {pA.z, pB.y, pC.x, pC.w};
        float qx[4] = {qA.x, qA.w, qB.z, qC.y};
        float qy[4] = {qA.y, qB.x, qB.w, qC.z};
        float qz[4] = {qA.z, qB.y, qC.x, qC.w};

        #pragma unroll
        for (int k = 0; k < 4; k++) {
            acc[0] += px[k]; acc[1] += py[k]; acc[2] += pz[k];
            acc[3] += qx[k]; acc[4] += qy[k]; acc[5] += qz[k];
            acc[6]  = fmaf(px[k], px[k], fmaf(py[k], py[k], fmaf(pz[k], pz[k], acc[6])));
            acc[7]  = fmaf(qx[k], qx[k], fmaf(qy[k], qy[k], fmaf(qz[k], qz[k], acc[7])));
            acc[8]  = fmaf(px[k], qx[k], acc[8]);
            acc[9]  = fmaf(px[k], qy[k], acc[9]);
            acc[10] = fmaf(px[k], qz[k], acc[10]);
            acc[11] = fmaf(py[k], qx[k], acc[11]);
            acc[12] = fmaf(py[k], qy[k], acc[12]);
            acc[13] = fmaf(py[k], qz[k], acc[13]);
            acc[14] = fmaf(pz[k], qx[k], acc[14]);
            acc[15] = fmaf(pz[k], qy[k], acc[15]);
            acc[16] = fmaf(pz[k], qz[k], acc[16]);
        }
    }

    // warp-local reduce; lane 0 ends up with the 17 batch scalars
    #pragma unroll
    for (int i = 0; i < 17; i++)
        acc[i] = warp_sum(acc[i]);

    if (lane == 0) {
        const float n = (float)NPTS;
        const float invn = 1.0f / n;
        float pm0 = acc[0] * invn, pm1 = acc[1] * invn, pm2 = acc[2] * invn;
        float qm0 = acc[3] * invn, qm1 = acc[4] * invn, qm2 = acc[5] * invn;
        float Ep = acc[6] - n * (pm0*pm0 + pm1*pm1 + pm2*pm2);
        float Ec = acc[7] - n * (qm0*qm0 + qm1*qm1 + qm2*qm2);

        float A0 = acc[8]  - n * pm0 * qm0;
        float A1 = acc[9]  - n * pm0 * qm1;
        float A2 = acc[10] - n * pm0 * qm2;
        float A3 = acc[11] - n * pm1 * qm0;
        float A4 = acc[12] - n * pm1 * qm1;
        float A5 = acc[13] - n * pm1 * qm2;
        float A6 = acc[14] - n * pm2 * qm0;
        float A7 = acc[15] - n * pm2 * qm1;
        float A8 = acc[16] - n * pm2 * qm2;

        float detA = A0 * (A4 * A8 - A5 * A7)
                   - A1 * (A3 * A8 - A5 * A6)
                   + A2 * (A3 * A7 - A4 * A6);

        // M = A^T A (symmetric PSD)
        float m00 = A0*A0 + A3*A3 + A6*A6;
        float m01 = A0*A1 + A3*A4 + A6*A7;
        float m02 = A0*A2 + A3*A5 + A6*A8;
        float m11 = A1*A1 + A4*A4 + A7*A7;
        float m12 = A1*A2 + A4*A5 + A7*A8;
        float m22 = A2*A2 + A5*A5 + A8*A8;

        float q  = (m00 + m11 + m22) * (1.0f/3.0f);
        float p1 = m01*m01 + m02*m02 + m12*m12;
        float p2 = (m00-q)*(m00-q) + (m11-q)*(m11-q) + (m22-q)*(m22-q) + 2.0f*p1;
        float e1, e2, e3;
        if (p2 < 1e-30f) {
            e1 = e2 = e3 = q;
        } else {
            float pp = sqrtf(p2 * (1.0f/6.0f));
            float inv = 1.0f / pp;
            float b00 = (m00 - q) * inv, b11 = (m11 - q) * inv, b22 = (m22 - q) * inv;
            float b01 = m01 * inv, b02 = m02 * inv, b12 = m12 * inv;
            float detB = b00 * (b11 * b22 - b12 * b12)
                       - b01 * (b01 * b22 - b12 * b02)
                       + b02 * (b01 * b12 - b11 * b02);
            float r = detB * 0.5f;
            r = fminf(1.0f, fmaxf(-1.0f, r));
            float phi = acosf(r) * (1.0f/3.0f);
            e1 = q + 2.0f * pp * cosf(phi);                       // largest
            e3 = q + 2.0f * pp * cosf(phi + 2.0943951023931953f); // smallest
            e2 = 3.0f * q - e1 - e3;
        }
        float s1 = sqrtf(fmaxf(e1, 0.f));
        float s2 = sqrtf(fmaxf(e2, 0.f));
        float s3 = sqrtf(fmaxf(e3, 0.f));
        float tr = s1 + s2 + ((detA >= 0.f) ? s3 : -s3);

        float msd = fmaxf(0.f, (Ep + Ec - 2.0f * tr) * invn);
        atomicAdd(&g_sum, sqrtf(msd));   // overlapped L2 accumulation
    }

    // -------- completion protocol: last CTA publishes the mean --------
    __shared__ bool s_last;
    __syncthreads();                     // all 8 warps' atomicAdds issued
    if (threadIdx.x == 0) {
        __threadfence();                 // order our adds before the counter
        unsigned int old = atomicAdd(&g_ctr, 1u);
        s_last = (old == (unsigned int)(ncta - 1));
    }
    __syncthreads();
    if (!s_last) return;

    if (threadIdx.x == 0) {
        __threadfence();                 // see all other CTAs' adds
        float total = atomicAdd(&g_sum, 0.0f);   // coherent L2 read
        out[0] = total / (float)B;
        g_sum = 0.f;                     // reset for next launch / graph replay
        __threadfence();
        g_ctr = 0;
    }
}

extern "C" void kernel_launch(void* const* d_in, const int* in_sizes, int n_in,
                              void* d_out, int out_size)
{
    const float* p = (const float*)d_in[0];   // coords_pred [B, N, 3]
    const float* c = (const float*)d_in[1];   // coords      [B, N, 3]
    const int B = in_sizes[0] / (NPTS * 3);
    const int ncta = B / 8;

    kabsch_kernel<<<ncta, 256>>>(p, c, (float*)d_out, B, ncta);
}

// round 10
// speedup vs baseline: 1.0693x; 1.0693x over previous
#include <cuda_runtime.h>
#include <cuda_bf16.h>
#include <math.h>

// Batched Kabsch RMSD — single fused kernel (R8 configuration, verified best):
//  - warp-per-batch streaming reduction (16 x 6 LDG.128 per lane, unroll 4)
//  - warp-local reduce; lane 0 runs fp32 closed-form 3x3 eigensolve -> g_rmsd[b]
//  - last-CTA-to-finish reduces all rmsds (L2-resident) -> out[0], resets counter

#define NPTS 2048
#define MAXB 8192

__device__ float g_rmsd[MAXB];
__device__ unsigned int g_ctr = 0;      // returns to 0 at end of every launch

__device__ __forceinline__ float warp_sum(float v) {
    #pragma unroll
    for (int o = 16; o > 0; o >>= 1)
        v += __shfl_down_sync(0xffffffffu, v, o);
    return v;
}

__global__ __launch_bounds__(256, 4)
void kabsch_kernel(const float* __restrict__ P,
                   const float* __restrict__ Q,
                   float* __restrict__ out,
                   int B, int ncta)
{
    const int lane = threadIdx.x & 31;
    const int wid  = threadIdx.x >> 5;
    const int b    = blockIdx.x * 8 + wid;

    const float4* pb = reinterpret_cast<const float4*>(P + (size_t)b * (NPTS * 3));
    const float4* qb = reinterpret_cast<const float4*>(Q + (size_t)b * (NPTS * 3));

    // acc: [0..2]=sum_p, [3..5]=sum_q, [6]=sum|p|^2, [7]=sum|q|^2,
    //      [8..16]=sum p_a*q_b (row-major)
    float acc[17];
    #pragma unroll
    for (int i = 0; i < 17; i++) acc[i] = 0.f;

    #pragma unroll 4
    for (int j = 0; j < 16; j++) {
        const int g = j * 32 + lane;              // group of 4 points
        float4 pA = __ldcs(&pb[3*g+0]);
        float4 pB = __ldcs(&pb[3*g+1]);
        float4 pC = __ldcs(&pb[3*g+2]);
        float4 qA = __ldcs(&qb[3*g+0]);
        float4 qB = __ldcs(&qb[3*g+1]);
        float4 qC = __ldcs(&qb[3*g+2]);

        float px[4] = {pA.x, pA.w, pB.z, pC.y};
        float py[4] = {pA.y, pB.x, pB.w, pC.z};
        float pz[4] = {pA.z, pB.y, pC.x, pC.w};
        float qx[4] = {qA.x, qA.w, qB.z, qC.y};
        float qy[4] = {qA.y, qB.x, qB.w, qC.z};
        float qz[4] = {qA.z, qB.y, qC.x, qC.w};

        #pragma unroll
        for (int k = 0; k < 4; k++) {
            acc[0] += px[k]; acc[1] += py[k]; acc[2] += pz[k];
            acc[3] += qx[k]; acc[4] += qy[k]; acc[5] += qz[k];
            acc[6]  = fmaf(px[k], px[k], fmaf(py[k], py[k], fmaf(pz[k], pz[k], acc[6])));
            acc[7]  = fmaf(qx[k], qx[k], fmaf(qy[k], qy[k], fmaf(qz[k], qz[k], acc[7])));
            acc[8]  = fmaf(px[k], qx[k], acc[8]);
            acc[9]  = fmaf(px[k], qy[k], acc[9]);
            acc[10] = fmaf(px[k], qz[k], acc[10]);
            acc[11] = fmaf(py[k], qx[k], acc[11]);
            acc[12] = fmaf(py[k], qy[k], acc[12]);
            acc[13] = fmaf(py[k], qz[k], acc[13]);
            acc[14] = fmaf(pz[k], qx[k], acc[14]);
            acc[15] = fmaf(pz[k], qy[k], acc[15]);
            acc[16] = fmaf(pz[k], qz[k], acc[16]);
        }
    }

    // warp-local reduce; lane 0 ends up with the 17 batch scalars
    #pragma unroll
    for (int i = 0; i < 17; i++)
        acc[i] = warp_sum(acc[i]);

    if (lane == 0) {
        const float n = (float)NPTS;
        const float invn = 1.0f / n;
        float pm0 = acc[0] * invn, pm1 = acc[1] * invn, pm2 = acc[2] * invn;
        float qm0 = acc[3] * invn, qm1 = acc[4] * invn, qm2 = acc[5] * invn;
        float Ep = acc[6] - n * (pm0*pm0 + pm1*pm1 + pm2*pm2);
        float Ec = acc[7] - n * (qm0*qm0 + qm1*qm1 + qm2*qm2);

        float A0 = acc[8]  - n * pm0 * qm0;
        float A1 = acc[9]  - n * pm0 * qm1;
        float A2 = acc[10] - n * pm0 * qm2;
        float A3 = acc[11] - n * pm1 * qm0;
        float A4 = acc[12] - n * pm1 * qm1;
        float A5 = acc[13] - n * pm1 * qm2;
        float A6 = acc[14] - n * pm2 * qm0;
        float A7 = acc[15] - n * pm2 * qm1;
        float A8 = acc[16] - n * pm2 * qm2;

        float detA = A0 * (A4 * A8 - A5 * A7)
                   - A1 * (A3 * A8 - A5 * A6)
                   + A2 * (A3 * A7 - A4 * A6);

        // M = A^T A (symmetric PSD)
        float m00 = A0*A0 + A3*A3 + A6*A6;
        float m01 = A0*A1 + A3*A4 + A6*A7;
        float m02 = A0*A2 + A3*A5 + A6*A8;
        float m11 = A1*A1 + A4*A4 + A7*A7;
        float m12 = A1*A2 + A4*A5 + A7*A8;
        float m22 = A2*A2 + A5*A5 + A8*A8;

        float q  = (m00 + m11 + m22) * (1.0f/3.0f);
        float p1 = m01*m01 + m02*m02 + m12*m12;
        float p2 = (m00-q)*(m00-q) + (m11-q)*(m11-q) + (m22-q)*(m22-q) + 2.0f*p1;
        float e1, e2, e3;
        if (p2 < 1e-30f) {
            e1 = e2 = e3 = q;
        } else {
            float pp = sqrtf(p2 * (1.0f/6.0f));
            float inv = 1.0f / pp;
            float b00 = (m00 - q) * inv, b11 = (m11 - q) * inv, b22 = (m22 - q) * inv;
            float b01 = m01 * inv, b02 = m02 * inv, b12 = m12 * inv;
            float detB = b00 * (b11 * b22 - b12 * b12)
                       - b01 * (b01 * b22 - b12 * b02)
                       + b02 * (b01 * b12 - b11 * b02);
            float r = detB * 0.5f;
            r = fminf(1.0f, fmaxf(-1.0f, r));
            float phi = acosf(r) * (1.0f/3.0f);
            e1 = q + 2.0f * pp * cosf(phi);                       // largest
            e3 = q + 2.0f * pp * cosf(phi + 2.0943951023931953f); // smallest
            e2 = 3.0f * q - e1 - e3;
        }
        float s1 = sqrtf(fmaxf(e1, 0.f));
        float s2 = sqrtf(fmaxf(e2, 0.f));
        float s3 = sqrtf(fmaxf(e3, 0.f));
        float tr = s1 + s2 + ((detA >= 0.f) ? s3 : -s3);

        float msd = fmaxf(0.f, (Ep + Ec - 2.0f * tr) * invn);
        g_rmsd[b] = sqrtf(msd);
    }

    // -------- last-CTA final reduction --------
    __shared__ bool s_last;
    __syncthreads();                    // all 8 warps' g_rmsd stores issued
    if (threadIdx.x == 0) {
        __threadfence();                // make our rmsd writes visible
        unsigned int old = atomicAdd(&g_ctr, 1u);
        s_last = (old == (unsigned int)(ncta - 1));
    }
    __syncthreads();
    if (!s_last) return;

    __threadfence();                    // acquire: see all other CTAs' writes

    // reduce B rmsds (L2-resident) with this CTA's 256 threads
    const float4* r4 = reinterpret_cast<const float4*>(g_rmsd);
    const int n4 = B >> 2;
    float s = 0.f;
    for (int i = threadIdx.x; i < n4; i += 256) {
        float4 v = r4[i];
        s += (v.x + v.y) + (v.z + v.w);
    }

    __shared__ float sm[8];
    s = warp_sum(s);
    if (lane == 0) sm[wid] = s;
    __syncthreads();
    if (wid == 0) {
        float v = (lane < 8) ? sm[lane] : 0.f;
        v += __shfl_down_sync(0xffffffffu, v, 4);
        v += __shfl_down_sync(0xffffffffu, v, 2);
        v += __shfl_down_sync(0xffffffffu, v, 1);
        if (lane == 0) {
            out[0] = v / (float)B;
            g_ctr = 0;                  // reset for next launch / graph replay
        }
    }
}

extern "C" void kernel_launch(void* const* d_in, const int* in_sizes, int n_in,
                              void* d_out, int out_size)
{
    const float* p = (const float*)d_in[0];   // coords_pred [B, N, 3]
    const float* c = (const float*)d_in[1];   // coords      [B, N, 3]
    const int B = in_sizes[0] / (NPTS * 3);
    const int ncta = B / 8;

    kabsch_kernel<<<ncta, 256>>>(p, c, (float*)d_out, B, ncta);
}